// round 4
// baseline (speedup 1.0000x reference)
#include <cuda_runtime.h>
#include <cuda_fp16.h>

// MedianBlur 5x5, fp32 I/O, 12 images of 1024x1024, zero padding (same).
// Round-4: smem tile stored PRE-PACKED as distance-2 half2 pairs
// P2[c] = (h[c], h[c+2]) in a group-interleaved layout p2t[r][c%4][c/4]
// so main-loop column loads are single conflict-free LDS.32 (no PRMT on the
// saturated alu pipe). 4 outputs/thread, candidate-band med25, explicit
// 12-op med7 finisher. __launch_bounds__(256,6).

#define IMG_H 1024
#define IMG_W 1024
#define NIMG  12

#define TILE_W 128            // output cols per block (32 threads * 4 px)
#define TILE_H 8              // output rows per block
#define SMEM_H 12             // TILE_H + 4 halo
#define KCOLS 34              // packed cols per group: c = 4*k + g, c in [0,136)

typedef __half2 h2;

__device__ __forceinline__ h2 mn2(h2 a, h2 b) { return __hmin2(a, b); }
__device__ __forceinline__ h2 mx2(h2 a, h2 b) { return __hmax2(a, b); }

__device__ __forceinline__ void ce(h2& a, h2& b) {
    h2 t = mn2(a, b);
    b = mx2(a, b);
    a = t;
}

// 9-CE optimal sorting network for 5 elements (ascending), element-wise on half2.
__device__ __forceinline__ void sort5(h2& v0, h2& v1, h2& v2, h2& v3, h2& v4) {
    ce(v0, v1); ce(v3, v4); ce(v2, v4); ce(v2, v3); ce(v0, v3);
    ce(v0, v2); ce(v1, v4); ce(v1, v3); ce(v1, v2);
}

// Merge sorted pair (a0<=a1) with sorted triple (b0<=b1<=b2) -> m0..m4.
__device__ __forceinline__ void merge23(h2 a0, h2 a1,
                                        h2 b0, h2 b1, h2 b2,
                                        h2& m0, h2& m1, h2& m2,
                                        h2& m3, h2& m4) {
    h2 x0 = mn2(a0, b0); h2 y0 = mx2(a0, b0);
    h2 x1 = mn2(y0, b1); h2 y1 = mx2(y0, b1);
    h2 x2 = mn2(y1, b2); h2 x3 = mx2(y1, b2);
    h2 w1 = mn2(a1, x1); h2 z1 = mx2(a1, x1);
    h2 w2 = mn2(z1, x2); h2 z2 = mx2(z1, x2);
    h2 w3 = mn2(z2, x3); h2 w4 = mx2(z2, x3);
    m0 = x0; m1 = w1; m2 = w2; m3 = w3; m4 = w4;
}

// Merge two sorted pairs -> m0..m3 (3 CE).
__device__ __forceinline__ void merge22(h2 a0, h2 a1, h2 b0, h2 b1,
                                        h2& m0, h2& m1, h2& m2, h2& m3) {
    m0 = mn2(a0, b0); h2 t = mx2(a0, b0);
    m3 = mx2(a1, b1); h2 u = mn2(a1, b1);
    m1 = mn2(t, u);   m2 = mx2(t, u);
}

// Batcher odd-even merge of two sorted triples -> z0..z5 (6 CE).
__device__ __forceinline__ void merge33(h2 a0, h2 a1, h2 a2,
                                        h2 b0, h2 b1, h2 b2,
                                        h2& z0, h2& z1, h2& z2,
                                        h2& z3, h2& z4, h2& z5) {
    h2 e0, e1, e2, e3;
    merge22(a0, a2, b0, b2, e0, e1, e2, e3);
    h2 o0 = a1, o1 = b1;
    ce(o0, o1);
    z0 = e0;
    z1 = o0; z2 = e1; ce(z1, z2);
    z3 = o1; z4 = e2; ce(z3, z4);
    z5 = e3;
}

// Batcher odd-even merge of two sorted 5-chains; only ranks 3..6 of 10 produced.
__device__ __forceinline__ void merge55_mid4(const h2 A[5], const h2 B[5],
                                             h2& s0, h2& s1, h2& s2, h2& s3) {
    h2 z0, z1, z2, z3, z4, z5;
    merge33(A[0], A[2], A[4], B[0], B[2], B[4], z0, z1, z2, z3, z4, z5);
    h2 w0, w1, w2, w3;
    merge22(A[1], A[3], B[1], B[3], w0, w1, w2, w3);
    s0 = mn2(w1, z2); s1 = mx2(w1, z2);
    s2 = mn2(w2, z3); s3 = mx2(w2, z3);
}

// Median of 5 (unordered), 10 ops: drop the provable-low and provable-high,
// then med3 of the remaining three.
__device__ __forceinline__ h2 med5(h2 v0, h2 v1, h2 v2, h2 v3, h2 v4) {
    ce(v0, v1); ce(v3, v4);            // v0<=v1, v3<=v4
    h2 a = mx2(v0, v3);                // min(v0,v3) has >=3 above -> drop
    h2 b = mn2(v1, v4);                // max(v1,v4) has >=3 below -> drop
    // med3(a, b, v2)
    h2 lo = mn2(a, b);
    h2 hi = mx2(a, b);
    return mx2(lo, mn2(hi, v2));
}

// Median of 25 given 5 ascending-sorted columns (element-wise on half2 lanes).
__device__ __forceinline__ h2 med25_from_sorted_cols(
    const h2 c0[5], const h2 c1[5], const h2 c2[5],
    const h2 c3[5], const h2 c4[5]) {
    h2 r0[5] = {c0[0], c1[0], c2[0], c3[0], c4[0]};
    h2 r1[5] = {c0[1], c1[1], c2[1], c3[1], c4[1]};
    h2 r2[5] = {c0[2], c1[2], c2[2], c3[2], c4[2]};
    h2 r3[5] = {c0[3], c1[3], c2[3], c3[3], c4[3]};
    h2 r4[5] = {c0[4], c1[4], c2[4], c3[4], c4[4]};
    sort5(r0[0], r0[1], r0[2], r0[3], r0[4]);
    sort5(r1[0], r1[1], r1[2], r1[3], r1[4]);
    sort5(r2[0], r2[1], r2[2], r2[3], r2[4]);
    sort5(r3[0], r3[1], r3[2], r3[3], r3[4]);
    sort5(r4[0], r4[1], r4[2], r4[3], r4[4]);

    // Candidate band (13 elems): r0[3..4], r1[2..4], r2[1..3], r3[0..2], r4[0..1]
    h2 A[5], B[5];
    merge23(r0[3], r0[4], r1[2], r1[3], r1[4], A[0], A[1], A[2], A[3], A[4]);
    merge23(r4[0], r4[1], r3[0], r3[1], r3[2], B[0], B[1], B[2], B[3], B[4]);

    h2 s0, s1, s2, s3;
    merge55_mid4(A, B, s0, s1, s2, s3);

    // med13 == med7({S[3..6], r2[1..3]}); drop global min & max -> med5.
    h2 u0 = mx2(s0, r2[1]);
    h2 u3 = mn2(s3, r2[3]);
    return med5(u0, s1, s2, u3, r2[2]);
}

__global__ __launch_bounds__(256, 6)
void median5x5_h2_kernel(const float* __restrict__ in, float* __restrict__ out) {
    // Packed tile: P2[c] = (h[c], h[c+2]), stored group-interleaved:
    // p2t[r][c & 3][c >> 2]. Main-loop reads stride 1 across lanes.
    __shared__ h2 p2t[SMEM_H][4][KCOLS];

    const int n   = blockIdx.z;
    const int x0b = blockIdx.x * TILE_W;
    const int y0b = blockIdx.y * TILE_H;
    const float* img = in + (size_t)n * IMG_H * IMG_W;

    const int tx = threadIdx.x;
    const int ty = threadIdx.y;
    const int tid = ty * 32 + tx;

    // Loader: iteration i handles k = i%KCOLS of row r = i/KCOLS, producing
    // P2[4k+g] for g=0..3 from floats gx0..gx0+5 (gx0 = x0b-4+4k).
    #pragma unroll
    for (int i = tid; i < SMEM_H * KCOLS; i += 256) {
        const int r  = i / KCOLS;
        const int k  = i - r * KCOLS;
        const int gy  = y0b + r - 2;
        const int gx0 = x0b - 4 + k * 4;
        float f0 = 0.f, f1 = 0.f, f2 = 0.f, f3 = 0.f, f4 = 0.f, f5 = 0.f;
        if ((unsigned)gy < IMG_H) {
            const float* rowp = img + (size_t)gy * IMG_W;
            if (gx0 >= 0 && gx0 + 5 < IMG_W) {
                const float4 fa = *reinterpret_cast<const float4*>(rowp + gx0);
                const float2 fb = *reinterpret_cast<const float2*>(rowp + gx0 + 4);
                f0 = fa.x; f1 = fa.y; f2 = fa.z; f3 = fa.w; f4 = fb.x; f5 = fb.y;
            } else {
                if ((unsigned)gx0       < IMG_W) f0 = rowp[gx0];
                if ((unsigned)(gx0 + 1) < IMG_W) f1 = rowp[gx0 + 1];
                if ((unsigned)(gx0 + 2) < IMG_W) f2 = rowp[gx0 + 2];
                if ((unsigned)(gx0 + 3) < IMG_W) f3 = rowp[gx0 + 3];
                if ((unsigned)(gx0 + 4) < IMG_W) f4 = rowp[gx0 + 4];
                if ((unsigned)(gx0 + 5) < IMG_W) f5 = rowp[gx0 + 5];
            }
        }
        p2t[r][0][k] = __float22half2_rn(make_float2(f0, f2));
        p2t[r][1][k] = __float22half2_rn(make_float2(f1, f3));
        p2t[r][2][k] = __float22half2_rn(make_float2(f2, f4));
        p2t[r][3][k] = __float22half2_rn(make_float2(f3, f5));
    }
    __syncthreads();

    // Thread handles pixels p0..p0+3 (p0 = tx*4) as pairs (p0,p0+2),(p0+1,p0+3).
    // Packed col m (m=0..5) is P2[p0+2+m]: group g=(2+m)&3, index k=tx+((2+m)>>2).
    // Network A (pixels p0,p0+2) uses cols 0..4; network B (p0+1,p0+3) cols 1..5.
    h2 col[6][5];
    #pragma unroll
    for (int m = 0; m < 6; m++) {
        const int g = (2 + m) & 3;
        const int kk = tx + ((2 + m) >> 2);
        #pragma unroll
        for (int i = 0; i < 5; i++)
            col[m][i] = p2t[ty + i][g][kk];
    }

    #pragma unroll
    for (int m = 0; m < 6; m++)
        sort5(col[m][0], col[m][1], col[m][2], col[m][3], col[m][4]);

    const h2 rA = med25_from_sorted_cols(col[0], col[1], col[2], col[3], col[4]);
    const h2 rB = med25_from_sorted_cols(col[1], col[2], col[3], col[4], col[5]);

    float4 res;
    res.x = __low2float(rA);    // pixel p0
    res.y = __low2float(rB);    // pixel p0+1
    res.z = __high2float(rA);   // pixel p0+2
    res.w = __high2float(rB);   // pixel p0+3

    float* orow = out + (size_t)n * IMG_H * IMG_W
                      + (size_t)(y0b + ty) * IMG_W + x0b + tx * 4;
    *reinterpret_cast<float4*>(orow) = res;
}

extern "C" void kernel_launch(void* const* d_in, const int* in_sizes, int n_in,
                              void* d_out, int out_size) {
    (void)in_sizes; (void)n_in; (void)out_size;
    const float* in = (const float*)d_in[0];
    float* out = (float*)d_out;

    dim3 block(32, TILE_H, 1);
    dim3 grid(IMG_W / TILE_W, IMG_H / TILE_H, NIMG);
    median5x5_h2_kernel<<<grid, block>>>(in, out);
}

// round 5
// speedup vs baseline: 1.2466x; 1.2466x over previous
#include <cuda_runtime.h>
#include <cuda_fp16.h>

// MedianBlur 5x5, fp32 I/O, 12 images of 1024x1024, zero padding (same).
// Round-5: shared row-sort4 between the two horizontal networks.
// Row i of network A = (c0..c4)[i], of B = (c1..c5)[i]: sort4 of the shared
// (c1..c4)[i] once, then rank-insert c0 (A) and c5 (B) producing only the
// candidate-band ranks. Hand-trimmed merge55_mid4 (16 ops) and med7 finisher
// (10 ops, exploiting s1<=s2). Packed half2 distance-2 pairs, 4 px/thread.

#define IMG_H 1024
#define IMG_W 1024
#define NIMG  12

#define TILE_W 128            // output cols per block (32 threads * 4 px)
#define TILE_H 8              // output rows per block
#define SMEM_H 12             // TILE_H + 4 halo
#define KCOLS 34              // packed cols per group: c = 4*k + g, c in [0,136)

typedef __half2 h2;

__device__ __forceinline__ h2 mn2(h2 a, h2 b) { return __hmin2(a, b); }
__device__ __forceinline__ h2 mx2(h2 a, h2 b) { return __hmax2(a, b); }

__device__ __forceinline__ void ce(h2& a, h2& b) {
    h2 t = mn2(a, b);
    b = mx2(a, b);
    a = t;
}

// 9-CE optimal sorting network for 5 elements (ascending), element-wise on half2.
__device__ __forceinline__ void sort5(h2& v0, h2& v1, h2& v2, h2& v3, h2& v4) {
    ce(v0, v1); ce(v3, v4); ce(v2, v4); ce(v2, v3); ce(v0, v3);
    ce(v0, v2); ce(v1, v4); ce(v1, v3); ce(v1, v2);
}

// 5-CE sorting network for 4 elements (ascending): a<=b<=c<=d on exit.
__device__ __forceinline__ void sort4(h2& a, h2& b, h2& c, h2& d) {
    ce(a, b); ce(c, d); ce(a, c); ce(b, d); ce(b, c);
}

// Merge sorted pair (a0<=a1) with sorted triple (b0<=b1<=b2) -> m0..m4.
__device__ __forceinline__ void merge23(h2 a0, h2 a1,
                                        h2 b0, h2 b1, h2 b2,
                                        h2& m0, h2& m1, h2& m2,
                                        h2& m3, h2& m4) {
    h2 x0 = mn2(a0, b0); h2 y0 = mx2(a0, b0);
    h2 x1 = mn2(y0, b1); h2 y1 = mx2(y0, b1);
    h2 x2 = mn2(y1, b2); h2 x3 = mx2(y1, b2);
    h2 w1 = mn2(a1, x1); h2 z1 = mx2(a1, x1);
    h2 w2 = mn2(z1, x2); h2 z2 = mx2(z1, x2);
    h2 w3 = mn2(z2, x3); h2 w4 = mx2(z2, x3);
    m0 = x0; m1 = w1; m2 = w2; m3 = w3; m4 = w4;
}

// Batcher merge of two sorted 5-chains, producing ONLY ranks 3..6 of 10.
// Hand-trimmed to the 16 live ops.
__device__ __forceinline__ void merge55_mid4(const h2 A[5], const h2 B[5],
                                             h2& s0, h2& s1, h2& s2, h2& s3) {
    // evens (A0,A2,A4)x(B0,B2,B4): need z2, z3 only.
    h2 t  = mx2(A[0], B[0]);
    h2 u  = mn2(A[4], B[4]);
    h2 e1 = mn2(t, u);
    h2 e2 = mx2(t, u);
    h2 o0 = mn2(A[2], B[2]);
    h2 o1 = mx2(A[2], B[2]);
    h2 z2 = mx2(o0, e1);
    h2 z3 = mn2(o1, e2);
    // odds (A1,A3)x(B1,B3): need w1, w2 only.
    h2 tt = mx2(A[1], B[1]);
    h2 uu = mn2(A[3], B[3]);
    h2 w1 = mn2(tt, uu);
    h2 w2 = mx2(tt, uu);
    s0 = mn2(w1, z2); s1 = mx2(w1, z2);
    s2 = mn2(w2, z3); s3 = mx2(w2, z3);
}

// Finisher: med13 == med7({s0<=s1<=s2<=s3} U {m0<=m1<=m2}).
// Drop global min (u0) & max (u3), then med5 of {u0, s1, s2, u3, m1}
// with the known pair s1<=s2 (saves one CE). 10 ops.
__device__ __forceinline__ h2 med7_fin(h2 s0, h2 s1, h2 s2, h2 s3,
                                       h2 m0, h2 m1, h2 m2) {
    h2 u0 = mx2(s0, m0);
    h2 u3 = mn2(s3, m2);
    h2 p = mn2(u3, m1);
    h2 q = mx2(u3, m1);
    h2 a = mx2(s1, p);   // v0=s1 (pre-sorted vs v1=s2), v3v4 = ce(u3,m1)
    h2 b = mn2(s2, q);
    h2 lo = mn2(a, b);
    h2 hi = mx2(a, b);
    return mx2(lo, mn2(hi, u0));   // med3(a, b, u0)
}

// Rank-insertion of x into sorted q0<=q1<=q2<=q3 (merge identities):
// y4=max(q3,x); y3=max(q2,min(q3,x)); y2=max(q1,min(q2,x));
// y1=max(q0,min(q1,x)); y0=min(q0,x).

__global__ __launch_bounds__(256, 6)
void median5x5_h2_kernel(const float* __restrict__ in, float* __restrict__ out) {
    // Packed tile: P2[c] = (h[c], h[c+2]), stored group-interleaved:
    // p2t[r][c & 3][c >> 2]. Main-loop reads stride 1 across lanes.
    __shared__ h2 p2t[SMEM_H][4][KCOLS];

    const int n   = blockIdx.z;
    const int x0b = blockIdx.x * TILE_W;
    const int y0b = blockIdx.y * TILE_H;
    const float* img = in + (size_t)n * IMG_H * IMG_W;

    const int tx = threadIdx.x;
    const int ty = threadIdx.y;
    const int tid = ty * 32 + tx;

    #pragma unroll
    for (int i = tid; i < SMEM_H * KCOLS; i += 256) {
        const int r  = i / KCOLS;
        const int k  = i - r * KCOLS;
        const int gy  = y0b + r - 2;
        const int gx0 = x0b - 4 + k * 4;
        float f0 = 0.f, f1 = 0.f, f2 = 0.f, f3 = 0.f, f4 = 0.f, f5 = 0.f;
        if ((unsigned)gy < IMG_H) {
            const float* rowp = img + (size_t)gy * IMG_W;
            if (gx0 >= 0 && gx0 + 5 < IMG_W) {
                const float4 fa = *reinterpret_cast<const float4*>(rowp + gx0);
                const float2 fb = *reinterpret_cast<const float2*>(rowp + gx0 + 4);
                f0 = fa.x; f1 = fa.y; f2 = fa.z; f3 = fa.w; f4 = fb.x; f5 = fb.y;
            } else {
                if ((unsigned)gx0       < IMG_W) f0 = rowp[gx0];
                if ((unsigned)(gx0 + 1) < IMG_W) f1 = rowp[gx0 + 1];
                if ((unsigned)(gx0 + 2) < IMG_W) f2 = rowp[gx0 + 2];
                if ((unsigned)(gx0 + 3) < IMG_W) f3 = rowp[gx0 + 3];
                if ((unsigned)(gx0 + 4) < IMG_W) f4 = rowp[gx0 + 4];
                if ((unsigned)(gx0 + 5) < IMG_W) f5 = rowp[gx0 + 5];
            }
        }
        p2t[r][0][k] = __float22half2_rn(make_float2(f0, f2));
        p2t[r][1][k] = __float22half2_rn(make_float2(f1, f3));
        p2t[r][2][k] = __float22half2_rn(make_float2(f2, f4));
        p2t[r][3][k] = __float22half2_rn(make_float2(f3, f5));
    }
    __syncthreads();

    // Thread handles pixels p0..p0+3 (p0 = tx*4) as pairs (p0,p0+2),(p0+1,p0+3).
    // Packed col m (m=0..5) is P2[p0+2+m]. Network A uses cols 0..4, B cols 1..5.
    h2 col[6][5];
    #pragma unroll
    for (int m = 0; m < 6; m++) {
        const int g = (2 + m) & 3;
        const int kk = tx + ((2 + m) >> 2);
        #pragma unroll
        for (int i = 0; i < 5; i++)
            col[m][i] = p2t[ty + i][g][kk];
    }

    #pragma unroll
    for (int m = 0; m < 6; m++)
        sort5(col[m][0], col[m][1], col[m][2], col[m][3], col[m][4]);

    // ---- Row phase: shared sort4 of cols 1..4 per row, rank-insert c0 / c5 ----
    // Band per network: r0 ranks{3,4}, r1 {2,3,4}, r2 {1,2,3}, r3 {0,1,2}, r4 {0,1}.
    h2 a03, a04, a12, a13, a14, aM1, aM2, aM3, a30, a31, a32, a40, a41;
    h2 b03, b04, b12, b13, b14, bM1, bM2, bM3, b30, b31, b32, b40, b41;

    {   // row 0: top2
        h2 q0 = col[1][0], q1 = col[2][0], q2 = col[3][0], q3 = col[4][0];
        sort4(q0, q1, q2, q3);
        h2 xa = col[0][0], xb = col[5][0];
        a04 = mx2(q3, xa); a03 = mx2(q2, mn2(q3, xa));
        b04 = mx2(q3, xb); b03 = mx2(q2, mn2(q3, xb));
    }
    {   // row 1: top3
        h2 q0 = col[1][1], q1 = col[2][1], q2 = col[3][1], q3 = col[4][1];
        sort4(q0, q1, q2, q3);
        h2 xa = col[0][1], xb = col[5][1];
        a14 = mx2(q3, xa); a13 = mx2(q2, mn2(q3, xa)); a12 = mx2(q1, mn2(q2, xa));
        b14 = mx2(q3, xb); b13 = mx2(q2, mn2(q3, xb)); b12 = mx2(q1, mn2(q2, xb));
    }
    {   // row 2: mid3 (ranks 1,2,3)
        h2 q0 = col[1][2], q1 = col[2][2], q2 = col[3][2], q3 = col[4][2];
        sort4(q0, q1, q2, q3);
        h2 xa = col[0][2], xb = col[5][2];
        aM3 = mx2(q2, mn2(q3, xa)); aM2 = mx2(q1, mn2(q2, xa)); aM1 = mx2(q0, mn2(q1, xa));
        bM3 = mx2(q2, mn2(q3, xb)); bM2 = mx2(q1, mn2(q2, xb)); bM1 = mx2(q0, mn2(q1, xb));
    }
    {   // row 3: bot3
        h2 q0 = col[1][3], q1 = col[2][3], q2 = col[3][3], q3 = col[4][3];
        sort4(q0, q1, q2, q3);
        h2 xa = col[0][3], xb = col[5][3];
        a30 = mn2(q0, xa); a31 = mx2(q0, mn2(q1, xa)); a32 = mx2(q1, mn2(q2, xa));
        b30 = mn2(q0, xb); b31 = mx2(q0, mn2(q1, xb)); b32 = mx2(q1, mn2(q2, xb));
    }
    {   // row 4: bot2
        h2 q0 = col[1][4], q1 = col[2][4], q2 = col[3][4], q3 = col[4][4];
        sort4(q0, q1, q2, q3);
        h2 xa = col[0][4], xb = col[5][4];
        a40 = mn2(q0, xa); a41 = mx2(q0, mn2(q1, xa));
        b40 = mn2(q0, xb); b41 = mx2(q0, mn2(q1, xb));
    }

    // ---- Merge phase per network ----
    h2 rA, rB;
    {
        h2 A[5], B[5];
        merge23(a03, a04, a12, a13, a14, A[0], A[1], A[2], A[3], A[4]);
        merge23(a40, a41, a30, a31, a32, B[0], B[1], B[2], B[3], B[4]);
        h2 s0, s1, s2, s3;
        merge55_mid4(A, B, s0, s1, s2, s3);
        rA = med7_fin(s0, s1, s2, s3, aM1, aM2, aM3);
    }
    {
        h2 A[5], B[5];
        merge23(b03, b04, b12, b13, b14, A[0], A[1], A[2], A[3], A[4]);
        merge23(b40, b41, b30, b31, b32, B[0], B[1], B[2], B[3], B[4]);
        h2 s0, s1, s2, s3;
        merge55_mid4(A, B, s0, s1, s2, s3);
        rB = med7_fin(s0, s1, s2, s3, bM1, bM2, bM3);
    }

    float4 res;
    res.x = __low2float(rA);    // pixel p0
    res.y = __low2float(rB);    // pixel p0+1
    res.z = __high2float(rA);   // pixel p0+2
    res.w = __high2float(rB);   // pixel p0+3

    float* orow = out + (size_t)n * IMG_H * IMG_W
                      + (size_t)(y0b + ty) * IMG_W + x0b + tx * 4;
    *reinterpret_cast<float4*>(orow) = res;
}

extern "C" void kernel_launch(void* const* d_in, const int* in_sizes, int n_in,
                              void* d_out, int out_size) {
    (void)in_sizes; (void)n_in; (void)out_size;
    const float* in = (const float*)d_in[0];
    float* out = (float*)d_out;

    dim3 block(32, TILE_H, 1);
    dim3 grid(IMG_W / TILE_W, IMG_H / TILE_H, NIMG);
    median5x5_h2_kernel<<<grid, block>>>(in, out);
}

// round 6
// speedup vs baseline: 1.2521x; 1.0044x over previous
#include <cuda_runtime.h>
#include <cuda_fp16.h>

// MedianBlur 5x5, fp32 I/O, 12 images of 1024x1024, zero padding (same).
// Round-6: constrained merges. Sorting rows of a column-sorted matrix
// preserves column order (r_i[k] <= r_{i+1}[k]), so the band merges
// (row0-top2 x row1-top3) and (row4-bot2 x row3-bot3) have known cross-chain
// dominances -> 6-op merges instead of 12. Partial row sorts (top2/bot2 of 4,
// drop-one-extreme sort4s). Packed half2 distance-2 pairs, 4 px/thread.

#define IMG_H 1024
#define IMG_W 1024
#define NIMG  12

#define TILE_W 128            // output cols per block (32 threads * 4 px)
#define TILE_H 8              // output rows per block
#define SMEM_H 12             // TILE_H + 4 halo
#define KCOLS 34              // packed cols per group: c = 4*k + g, c in [0,136)

typedef __half2 h2;

__device__ __forceinline__ h2 mn2(h2 a, h2 b) { return __hmin2(a, b); }
__device__ __forceinline__ h2 mx2(h2 a, h2 b) { return __hmax2(a, b); }

__device__ __forceinline__ void ce(h2& a, h2& b) {
    h2 t = mn2(a, b);
    b = mx2(a, b);
    a = t;
}

// 9-CE optimal sorting network for 5 elements (ascending), element-wise on half2.
__device__ __forceinline__ void sort5(h2& v0, h2& v1, h2& v2, h2& v3, h2& v4) {
    ce(v0, v1); ce(v3, v4); ce(v2, v4); ce(v2, v3); ce(v0, v3);
    ce(v0, v2); ce(v1, v4); ce(v1, v3); ce(v1, v2);
}

// Constrained merge of top chains: x0<=x1 (row i ranks {3,4}),
// y0<=y1<=y2 (row i+1 ranks {2,3,4}), with x0<=y1 and x1<=y2
// (column order of the doubly-sorted matrix). 6 ops.
__device__ __forceinline__ void merge_top(h2 x0, h2 x1, h2 y0, h2 y1, h2 y2,
                                          h2 A[5]) {
    A[0] = mn2(x0, y0);
    h2 p = mx2(x0, y0);
    A[3] = mx2(x1, y1);
    h2 q = mn2(x1, y1);
    A[1] = mn2(p, q);
    A[2] = mx2(p, q);
    A[4] = y2;
}

// Constrained merge of bottom chains: x0<=x1 (row i+1 ranks {0,1}),
// y0<=y1<=y2 (row i ranks {0,1,2}), with y0<=x0 and y1<=x1. 6 ops.
__device__ __forceinline__ void merge_bot(h2 x0, h2 x1, h2 y0, h2 y1, h2 y2,
                                          h2 B[5]) {
    B[0] = y0;
    B[1] = mn2(x0, y1);
    h2 p = mx2(x0, y1);
    h2 q = mn2(x1, y2);
    B[2] = mn2(p, q);
    B[3] = mx2(p, q);
    B[4] = mx2(x1, y2);
}

// Batcher merge of two sorted 5-chains, producing ONLY ranks 3..6 of 10. 16 ops.
__device__ __forceinline__ void merge55_mid4(const h2 A[5], const h2 B[5],
                                             h2& s0, h2& s1, h2& s2, h2& s3) {
    h2 t  = mx2(A[0], B[0]);
    h2 u  = mn2(A[4], B[4]);
    h2 e1 = mn2(t, u);
    h2 e2 = mx2(t, u);
    h2 o0 = mn2(A[2], B[2]);
    h2 o1 = mx2(A[2], B[2]);
    h2 z2 = mx2(o0, e1);
    h2 z3 = mn2(o1, e2);
    h2 tt = mx2(A[1], B[1]);
    h2 uu = mn2(A[3], B[3]);
    h2 w1 = mn2(tt, uu);
    h2 w2 = mx2(tt, uu);
    s0 = mn2(w1, z2); s1 = mx2(w1, z2);
    s2 = mn2(w2, z3); s3 = mx2(w2, z3);
}

// Finisher: med13 == med7({s0<=s1<=s2<=s3} U {m0<=m1<=m2}). 10 ops.
__device__ __forceinline__ h2 med7_fin(h2 s0, h2 s1, h2 s2, h2 s3,
                                       h2 m0, h2 m1, h2 m2) {
    h2 u0 = mx2(s0, m0);
    h2 u3 = mn2(s3, m2);
    h2 p = mn2(u3, m1);
    h2 q = mx2(u3, m1);
    h2 a = mx2(s1, p);
    h2 b = mn2(s2, q);
    h2 lo = mn2(a, b);
    h2 hi = mx2(a, b);
    return mx2(lo, mn2(hi, u0));
}

__global__ __launch_bounds__(256, 6)
void median5x5_h2_kernel(const float* __restrict__ in, float* __restrict__ out) {
    // Packed tile: P2[c] = (h[c], h[c+2]), stored group-interleaved:
    // p2t[r][c & 3][c >> 2]. Main-loop reads stride 1 across lanes.
    __shared__ h2 p2t[SMEM_H][4][KCOLS];

    const int n   = blockIdx.z;
    const int x0b = blockIdx.x * TILE_W;
    const int y0b = blockIdx.y * TILE_H;
    const float* img = in + (size_t)n * IMG_H * IMG_W;

    const int tx = threadIdx.x;
    const int ty = threadIdx.y;
    const int tid = ty * 32 + tx;

    #pragma unroll
    for (int i = tid; i < SMEM_H * KCOLS; i += 256) {
        const int r  = i / KCOLS;
        const int k  = i - r * KCOLS;
        const int gy  = y0b + r - 2;
        const int gx0 = x0b - 4 + k * 4;
        float f0 = 0.f, f1 = 0.f, f2 = 0.f, f3 = 0.f, f4 = 0.f, f5 = 0.f;
        if ((unsigned)gy < IMG_H) {
            const float* rowp = img + (size_t)gy * IMG_W;
            if (gx0 >= 0 && gx0 + 5 < IMG_W) {
                const float4 fa = *reinterpret_cast<const float4*>(rowp + gx0);
                const float2 fb = *reinterpret_cast<const float2*>(rowp + gx0 + 4);
                f0 = fa.x; f1 = fa.y; f2 = fa.z; f3 = fa.w; f4 = fb.x; f5 = fb.y;
            } else {
                if ((unsigned)gx0       < IMG_W) f0 = rowp[gx0];
                if ((unsigned)(gx0 + 1) < IMG_W) f1 = rowp[gx0 + 1];
                if ((unsigned)(gx0 + 2) < IMG_W) f2 = rowp[gx0 + 2];
                if ((unsigned)(gx0 + 3) < IMG_W) f3 = rowp[gx0 + 3];
                if ((unsigned)(gx0 + 4) < IMG_W) f4 = rowp[gx0 + 4];
                if ((unsigned)(gx0 + 5) < IMG_W) f5 = rowp[gx0 + 5];
            }
        }
        p2t[r][0][k] = __float22half2_rn(make_float2(f0, f2));
        p2t[r][1][k] = __float22half2_rn(make_float2(f1, f3));
        p2t[r][2][k] = __float22half2_rn(make_float2(f2, f4));
        p2t[r][3][k] = __float22half2_rn(make_float2(f3, f5));
    }
    __syncthreads();

    // Thread handles pixels p0..p0+3 (p0 = tx*4) as pairs (p0,p0+2),(p0+1,p0+3).
    // Packed col m (m=0..5) is P2[p0+2+m]. Network A uses cols 0..4, B cols 1..5.
    h2 col[6][5];
    #pragma unroll
    for (int m = 0; m < 6; m++) {
        const int g = (2 + m) & 3;
        const int kk = tx + ((2 + m) >> 2);
        #pragma unroll
        for (int i = 0; i < 5; i++)
            col[m][i] = p2t[ty + i][g][kk];
    }

    #pragma unroll
    for (int m = 0; m < 6; m++)
        sort5(col[m][0], col[m][1], col[m][2], col[m][3], col[m][4]);

    // ---- Row phase: partial shared sorts of cols 1..4, rank-insert c0 / c5 ----
    // Band per network: r0 ranks{3,4}, r1 {2,3,4}, r2 {1,2,3}, r3 {0,1,2}, r4 {0,1}.
    h2 a03, a04, a12, a13, a14, aM1, aM2, aM3, a30, a31, a32, a40, a41;
    h2 b03, b04, b12, b13, b14, bM1, bM2, bM3, b30, b31, b32, b40, b41;

    {   // row 0: top2 of 4 (8 ops), then insert top2 ranks
        h2 a = mn2(col[1][0], col[2][0]), b = mx2(col[1][0], col[2][0]);
        h2 c = mn2(col[3][0], col[4][0]), d = mx2(col[3][0], col[4][0]);
        h2 q3 = mx2(b, d);
        h2 q2 = mx2(mn2(b, d), mx2(a, c));
        h2 xa = col[0][0], xb = col[5][0];
        a04 = mx2(q3, xa); a03 = mx2(q2, mn2(q3, xa));
        b04 = mx2(q3, xb); b03 = mx2(q2, mn2(q3, xb));
    }
    {   // row 1: sort4 minus q0 (9 ops), insert -> ranks {2,3,4}
        h2 v0 = col[1][1], v1 = col[2][1], v2 = col[3][1], v3 = col[4][1];
        ce(v0, v1); ce(v2, v3);
        v2 = mx2(v0, v2);          // q0 (min side) unused
        ce(v1, v3); ce(v1, v2);
        const h2 q1 = v1, q2 = v2, q3 = v3;
        h2 xa = col[0][1], xb = col[5][1];
        a14 = mx2(q3, xa); a13 = mx2(q2, mn2(q3, xa)); a12 = mx2(q1, mn2(q2, xa));
        b14 = mx2(q3, xb); b13 = mx2(q2, mn2(q3, xb)); b12 = mx2(q1, mn2(q2, xb));
    }
    {   // row 2: full sort4 (10 ops), insert -> mid3 ranks {1,2,3}
        h2 q0 = col[1][2], q1 = col[2][2], q2 = col[3][2], q3 = col[4][2];
        ce(q0, q1); ce(q2, q3); ce(q0, q2); ce(q1, q3); ce(q1, q2);
        h2 xa = col[0][2], xb = col[5][2];
        aM3 = mx2(q2, mn2(q3, xa)); aM2 = mx2(q1, mn2(q2, xa)); aM1 = mx2(q0, mn2(q1, xa));
        bM3 = mx2(q2, mn2(q3, xb)); bM2 = mx2(q1, mn2(q2, xb)); bM1 = mx2(q0, mn2(q1, xb));
    }
    {   // row 3: sort4 minus q3 (9 ops), insert -> ranks {0,1,2}
        h2 v0 = col[1][3], v1 = col[2][3], v2 = col[3][3], v3 = col[4][3];
        ce(v0, v1); ce(v2, v3); ce(v0, v2);
        v1 = mn2(v1, v3);          // q3 (max side) unused
        ce(v1, v2);
        const h2 q0 = v0, q1 = v1, q2 = v2;
        h2 xa = col[0][3], xb = col[5][3];
        a30 = mn2(q0, xa); a31 = mx2(q0, mn2(q1, xa)); a32 = mx2(q1, mn2(q2, xa));
        b30 = mn2(q0, xb); b31 = mx2(q0, mn2(q1, xb)); b32 = mx2(q1, mn2(q2, xb));
    }
    {   // row 4: bottom2 of 4 (8 ops), insert -> ranks {0,1}
        h2 a = mn2(col[1][4], col[2][4]), b = mx2(col[1][4], col[2][4]);
        h2 c = mn2(col[3][4], col[4][4]), d = mx2(col[3][4], col[4][4]);
        h2 q0 = mn2(a, c);
        h2 q1 = mn2(mx2(a, c), mn2(b, d));
        h2 xa = col[0][4], xb = col[5][4];
        a40 = mn2(q0, xa); a41 = mx2(q0, mn2(q1, xa));
        b40 = mn2(q0, xb); b41 = mx2(q0, mn2(q1, xb));
    }

    // ---- Merge phase per network (constrained merges) ----
    h2 rA, rB;
    {
        h2 A[5], B[5];
        merge_top(a03, a04, a12, a13, a14, A);   // x<=y column dominance
        merge_bot(a40, a41, a30, a31, a32, B);   // y<=x column dominance
        h2 s0, s1, s2, s3;
        merge55_mid4(A, B, s0, s1, s2, s3);
        rA = med7_fin(s0, s1, s2, s3, aM1, aM2, aM3);
    }
    {
        h2 A[5], B[5];
        merge_top(b03, b04, b12, b13, b14, A);
        merge_bot(b40, b41, b30, b31, b32, B);
        h2 s0, s1, s2, s3;
        merge55_mid4(A, B, s0, s1, s2, s3);
        rB = med7_fin(s0, s1, s2, s3, bM1, bM2, bM3);
    }

    float4 res;
    res.x = __low2float(rA);    // pixel p0
    res.y = __low2float(rB);    // pixel p0+1
    res.z = __high2float(rA);   // pixel p0+2
    res.w = __high2float(rB);   // pixel p0+3

    float* orow = out + (size_t)n * IMG_H * IMG_W
                      + (size_t)(y0b + ty) * IMG_W + x0b + tx * 4;
    *reinterpret_cast<float4*>(orow) = res;
}

extern "C" void kernel_launch(void* const* d_in, const int* in_sizes, int n_in,
                              void* d_out, int out_size) {
    (void)in_sizes; (void)n_in; (void)out_size;
    const float* in = (const float*)d_in[0];
    float* out = (float*)d_out;

    dim3 block(32, TILE_H, 1);
    dim3 grid(IMG_W / TILE_W, IMG_H / TILE_H, NIMG);
    median5x5_h2_kernel<<<grid, block>>>(in, out);
}

// round 7
// speedup vs baseline: 1.2712x; 1.0153x over previous
#include <cuda_runtime.h>
#include <cuda_fp16.h>

// MedianBlur 5x5, fp32 I/O, 12 images of 1024x1024, zero padding (same).
// Round-7: wide-LDS layout. Packed tile p2t[r][k][g] with the 4 interleave
// groups contiguous (16B), so each window row is read with ONE LDS.64
// (cols m=0,1) + ONE LDS.128 (cols m=2..5): 10 LDS/thread instead of 30.
// Loader writes one STS.128 per (r,k) task. Network identical to round 6
// (constrained merges, partial row sorts) -> rel_err bit-identical.

#define IMG_H 1024
#define IMG_W 1024
#define NIMG  12

#define TILE_W 128            // output cols per block (32 threads * 4 px)
#define TILE_H 8              // output rows per block
#define SMEM_H 12             // TILE_H + 4 halo
#define KCOLS 34              // packed cols per group: c = 4*k + g, c in [0,136)

typedef __half2 h2;

__device__ __forceinline__ h2 mn2(h2 a, h2 b) { return __hmin2(a, b); }
__device__ __forceinline__ h2 mx2(h2 a, h2 b) { return __hmax2(a, b); }

__device__ __forceinline__ void ce(h2& a, h2& b) {
    h2 t = mn2(a, b);
    b = mx2(a, b);
    a = t;
}

// 9-CE optimal sorting network for 5 elements (ascending), element-wise on half2.
__device__ __forceinline__ void sort5(h2& v0, h2& v1, h2& v2, h2& v3, h2& v4) {
    ce(v0, v1); ce(v3, v4); ce(v2, v4); ce(v2, v3); ce(v0, v3);
    ce(v0, v2); ce(v1, v4); ce(v1, v3); ce(v1, v2);
}

// Constrained merge of top chains: x0<=x1 (row i ranks {3,4}),
// y0<=y1<=y2 (row i+1 ranks {2,3,4}), with x0<=y1 and x1<=y2. 6 ops.
__device__ __forceinline__ void merge_top(h2 x0, h2 x1, h2 y0, h2 y1, h2 y2,
                                          h2 A[5]) {
    A[0] = mn2(x0, y0);
    h2 p = mx2(x0, y0);
    A[3] = mx2(x1, y1);
    h2 q = mn2(x1, y1);
    A[1] = mn2(p, q);
    A[2] = mx2(p, q);
    A[4] = y2;
}

// Constrained merge of bottom chains: x0<=x1 (row i+1 ranks {0,1}),
// y0<=y1<=y2 (row i ranks {0,1,2}), with y0<=x0 and y1<=x1. 6 ops.
__device__ __forceinline__ void merge_bot(h2 x0, h2 x1, h2 y0, h2 y1, h2 y2,
                                          h2 B[5]) {
    B[0] = y0;
    B[1] = mn2(x0, y1);
    h2 p = mx2(x0, y1);
    h2 q = mn2(x1, y2);
    B[2] = mn2(p, q);
    B[3] = mx2(p, q);
    B[4] = mx2(x1, y2);
}

// Batcher merge of two sorted 5-chains, producing ONLY ranks 3..6 of 10. 16 ops.
__device__ __forceinline__ void merge55_mid4(const h2 A[5], const h2 B[5],
                                             h2& s0, h2& s1, h2& s2, h2& s3) {
    h2 t  = mx2(A[0], B[0]);
    h2 u  = mn2(A[4], B[4]);
    h2 e1 = mn2(t, u);
    h2 e2 = mx2(t, u);
    h2 o0 = mn2(A[2], B[2]);
    h2 o1 = mx2(A[2], B[2]);
    h2 z2 = mx2(o0, e1);
    h2 z3 = mn2(o1, e2);
    h2 tt = mx2(A[1], B[1]);
    h2 uu = mn2(A[3], B[3]);
    h2 w1 = mn2(tt, uu);
    h2 w2 = mx2(tt, uu);
    s0 = mn2(w1, z2); s1 = mx2(w1, z2);
    s2 = mn2(w2, z3); s3 = mx2(w2, z3);
}

// Finisher: med13 == med7({s0<=s1<=s2<=s3} U {m0<=m1<=m2}). 10 ops.
__device__ __forceinline__ h2 med7_fin(h2 s0, h2 s1, h2 s2, h2 s3,
                                       h2 m0, h2 m1, h2 m2) {
    h2 u0 = mx2(s0, m0);
    h2 u3 = mn2(s3, m2);
    h2 p = mn2(u3, m1);
    h2 q = mx2(u3, m1);
    h2 a = mx2(s1, p);
    h2 b = mn2(s2, q);
    h2 lo = mn2(a, b);
    h2 hi = mx2(a, b);
    return mx2(lo, mn2(hi, u0));
}

__global__ __launch_bounds__(256, 6)
void median5x5_h2_kernel(const float* __restrict__ in, float* __restrict__ out) {
    // Packed tile: P2[c] = (h[c], h[c+2]), c = 4k + g, stored p2t[r][k][g]
    // with g contiguous -> 16-byte groups readable by LDS.128 / LDS.64.
    __shared__ __align__(16) h2 p2t[SMEM_H][KCOLS][4];

    const int n   = blockIdx.z;
    const int x0b = blockIdx.x * TILE_W;
    const int y0b = blockIdx.y * TILE_H;
    const float* img = in + (size_t)n * IMG_H * IMG_W;

    const int tx = threadIdx.x;
    const int ty = threadIdx.y;
    const int tid = ty * 32 + tx;

    #pragma unroll
    for (int i = tid; i < SMEM_H * KCOLS; i += 256) {
        const int r  = i / KCOLS;
        const int k  = i - r * KCOLS;
        const int gy  = y0b + r - 2;
        const int gx0 = x0b - 4 + k * 4;
        float f0 = 0.f, f1 = 0.f, f2 = 0.f, f3 = 0.f, f4 = 0.f, f5 = 0.f;
        if ((unsigned)gy < IMG_H) {
            const float* rowp = img + (size_t)gy * IMG_W;
            if (gx0 >= 0 && gx0 + 5 < IMG_W) {
                const float4 fa = *reinterpret_cast<const float4*>(rowp + gx0);
                const float2 fb = *reinterpret_cast<const float2*>(rowp + gx0 + 4);
                f0 = fa.x; f1 = fa.y; f2 = fa.z; f3 = fa.w; f4 = fb.x; f5 = fb.y;
            } else {
                if ((unsigned)gx0       < IMG_W) f0 = rowp[gx0];
                if ((unsigned)(gx0 + 1) < IMG_W) f1 = rowp[gx0 + 1];
                if ((unsigned)(gx0 + 2) < IMG_W) f2 = rowp[gx0 + 2];
                if ((unsigned)(gx0 + 3) < IMG_W) f3 = rowp[gx0 + 3];
                if ((unsigned)(gx0 + 4) < IMG_W) f4 = rowp[gx0 + 4];
                if ((unsigned)(gx0 + 5) < IMG_W) f5 = rowp[gx0 + 5];
            }
        }
        const h2 p0 = __float22half2_rn(make_float2(f0, f2));
        const h2 p1 = __float22half2_rn(make_float2(f1, f3));
        const h2 p2 = __float22half2_rn(make_float2(f2, f4));
        const h2 p3 = __float22half2_rn(make_float2(f3, f5));
        uint4 w;
        w.x = *reinterpret_cast<const unsigned*>(&p0);
        w.y = *reinterpret_cast<const unsigned*>(&p1);
        w.z = *reinterpret_cast<const unsigned*>(&p2);
        w.w = *reinterpret_cast<const unsigned*>(&p3);
        *reinterpret_cast<uint4*>(&p2t[r][k][0]) = w;
    }
    __syncthreads();

    // Thread handles pixels p0..p0+3 (p0 = tx*4) as pairs (p0,p0+2),(p0+1,p0+3).
    // Packed col m (m=0..5) is P2[4tx+2+m]:
    //   m=0,1 -> p2t[row][tx][2..3]   (one LDS.64)
    //   m=2..5 -> p2t[row][tx+1][0..3] (one LDS.128)
    h2 col[6][5];
    #pragma unroll
    for (int i = 0; i < 5; i++) {
        const uint2 lo = *reinterpret_cast<const uint2*>(&p2t[ty + i][tx][2]);
        const uint4 hi = *reinterpret_cast<const uint4*>(&p2t[ty + i][tx + 1][0]);
        col[0][i] = *reinterpret_cast<const h2*>(&lo.x);
        col[1][i] = *reinterpret_cast<const h2*>(&lo.y);
        col[2][i] = *reinterpret_cast<const h2*>(&hi.x);
        col[3][i] = *reinterpret_cast<const h2*>(&hi.y);
        col[4][i] = *reinterpret_cast<const h2*>(&hi.z);
        col[5][i] = *reinterpret_cast<const h2*>(&hi.w);
    }

    #pragma unroll
    for (int m = 0; m < 6; m++)
        sort5(col[m][0], col[m][1], col[m][2], col[m][3], col[m][4]);

    // ---- Row phase: partial shared sorts of cols 1..4, rank-insert c0 / c5 ----
    h2 a03, a04, a12, a13, a14, aM1, aM2, aM3, a30, a31, a32, a40, a41;
    h2 b03, b04, b12, b13, b14, bM1, bM2, bM3, b30, b31, b32, b40, b41;

    {   // row 0: top2 of 4, insert -> ranks {3,4}
        h2 a = mn2(col[1][0], col[2][0]), b = mx2(col[1][0], col[2][0]);
        h2 c = mn2(col[3][0], col[4][0]), d = mx2(col[3][0], col[4][0]);
        h2 q3 = mx2(b, d);
        h2 q2 = mx2(mn2(b, d), mx2(a, c));
        h2 xa = col[0][0], xb = col[5][0];
        a04 = mx2(q3, xa); a03 = mx2(q2, mn2(q3, xa));
        b04 = mx2(q3, xb); b03 = mx2(q2, mn2(q3, xb));
    }
    {   // row 1: sort4 minus q0, insert -> ranks {2,3,4}
        h2 v0 = col[1][1], v1 = col[2][1], v2 = col[3][1], v3 = col[4][1];
        ce(v0, v1); ce(v2, v3);
        v2 = mx2(v0, v2);
        ce(v1, v3); ce(v1, v2);
        const h2 q1 = v1, q2 = v2, q3 = v3;
        h2 xa = col[0][1], xb = col[5][1];
        a14 = mx2(q3, xa); a13 = mx2(q2, mn2(q3, xa)); a12 = mx2(q1, mn2(q2, xa));
        b14 = mx2(q3, xb); b13 = mx2(q2, mn2(q3, xb)); b12 = mx2(q1, mn2(q2, xb));
    }
    {   // row 2: full sort4, insert -> mid3 ranks {1,2,3}
        h2 q0 = col[1][2], q1 = col[2][2], q2 = col[3][2], q3 = col[4][2];
        ce(q0, q1); ce(q2, q3); ce(q0, q2); ce(q1, q3); ce(q1, q2);
        h2 xa = col[0][2], xb = col[5][2];
        aM3 = mx2(q2, mn2(q3, xa)); aM2 = mx2(q1, mn2(q2, xa)); aM1 = mx2(q0, mn2(q1, xa));
        bM3 = mx2(q2, mn2(q3, xb)); bM2 = mx2(q1, mn2(q2, xb)); bM1 = mx2(q0, mn2(q1, xb));
    }
    {   // row 3: sort4 minus q3, insert -> ranks {0,1,2}
        h2 v0 = col[1][3], v1 = col[2][3], v2 = col[3][3], v3 = col[4][3];
        ce(v0, v1); ce(v2, v3); ce(v0, v2);
        v1 = mn2(v1, v3);
        ce(v1, v2);
        const h2 q0 = v0, q1 = v1, q2 = v2;
        h2 xa = col[0][3], xb = col[5][3];
        a30 = mn2(q0, xa); a31 = mx2(q0, mn2(q1, xa)); a32 = mx2(q1, mn2(q2, xa));
        b30 = mn2(q0, xb); b31 = mx2(q0, mn2(q1, xb)); b32 = mx2(q1, mn2(q2, xb));
    }
    {   // row 4: bottom2 of 4, insert -> ranks {0,1}
        h2 a = mn2(col[1][4], col[2][4]), b = mx2(col[1][4], col[2][4]);
        h2 c = mn2(col[3][4], col[4][4]), d = mx2(col[3][4], col[4][4]);
        h2 q0 = mn2(a, c);
        h2 q1 = mn2(mx2(a, c), mn2(b, d));
        h2 xa = col[0][4], xb = col[5][4];
        a40 = mn2(q0, xa); a41 = mx2(q0, mn2(q1, xa));
        b40 = mn2(q0, xb); b41 = mx2(q0, mn2(q1, xb));
    }

    // ---- Merge phase per network (constrained merges) ----
    h2 rA, rB;
    {
        h2 A[5], B[5];
        merge_top(a03, a04, a12, a13, a14, A);
        merge_bot(a40, a41, a30, a31, a32, B);
        h2 s0, s1, s2, s3;
        merge55_mid4(A, B, s0, s1, s2, s3);
        rA = med7_fin(s0, s1, s2, s3, aM1, aM2, aM3);
    }
    {
        h2 A[5], B[5];
        merge_top(b03, b04, b12, b13, b14, A);
        merge_bot(b40, b41, b30, b31, b32, B);
        h2 s0, s1, s2, s3;
        merge55_mid4(A, B, s0, s1, s2, s3);
        rB = med7_fin(s0, s1, s2, s3, bM1, bM2, bM3);
    }

    float4 res;
    res.x = __low2float(rA);    // pixel p0
    res.y = __low2float(rB);    // pixel p0+1
    res.z = __high2float(rA);   // pixel p0+2
    res.w = __high2float(rB);   // pixel p0+3

    float* orow = out + (size_t)n * IMG_H * IMG_W
                      + (size_t)(y0b + ty) * IMG_W + x0b + tx * 4;
    *reinterpret_cast<float4*>(orow) = res;
}

extern "C" void kernel_launch(void* const* d_in, const int* in_sizes, int n_in,
                              void* d_out, int out_size) {
    (void)in_sizes; (void)n_in; (void)out_size;
    const float* in = (const float*)d_in[0];
    float* out = (float*)d_out;

    dim3 block(32, TILE_H, 1);
    dim3 grid(IMG_W / TILE_W, IMG_H / TILE_H, NIMG);
    median5x5_h2_kernel<<<grid, block>>>(in, out);
}